// round 6
// baseline (speedup 1.0000x reference)
#include <cuda_runtime.h>

#define NB 4
#define DK 256
#define DV 516
#define HW 4096
#define LM 32
#define DS 4            // d-splits inside attn block
#define DQ 4            // d-splits across gridDim.y (64 d per block)

// temp = log2(32*64*64 + 64*64) / sqrt(256)
#define TEMP 1.06527463f

// Scratch (static device allocations only; no cudaMalloc anywhere)
__device__ float g_q[NB * DK * HW];            // 16 MB: q[b][d][hw], pre-scaled
__device__ float g_attn[NB * LM * HW];         // 2 MB:  attn[b][m][hw]
__device__ float g_part[DQ * NB * LM * HW];    // 8 MB:  partial scores

// ---------------------------------------------------------------------------
// Kernel 1: q[b][d][hw] = TEMP * sum_c Q[c][d] * fc[b][c][hw]
// 128x128 block tile, BK=8, 256 threads, 8x8 register tile, double-buffered
// smem with register prefetch -> one __syncthreads per k-tile.
// ---------------------------------------------------------------------------
__global__ __launch_bounds__(256) void qproj_kernel(
    const float* __restrict__ fc, const float* __restrict__ Qm) {
    __shared__ float As[2][8][128];   // [buf][c][d]
    __shared__ float Bs[2][8][128];   // [buf][c][hw]

    const int b   = blockIdx.z;
    const int d0  = blockIdx.y * 128;
    const int hw0 = blockIdx.x * 128;
    const int tid = threadIdx.x;
    const int tx  = tid & 15;        // hw tile coord (x8)
    const int ty  = tid >> 4;        // d  tile coord (x8)

    const float* fcb = fc + (size_t)b * DK * HW;

    const int lr = tid >> 5;          // 0..7  (c within tile)
    const int lc = (tid & 31) * 4;    // 0..124

    float acc[8][8];
#pragma unroll
    for (int i = 0; i < 8; i++)
#pragma unroll
        for (int j = 0; j < 8; j++) acc[i][j] = 0.0f;

    float4 pa = *(const float4*)(Qm + (size_t)lr * DK + d0 + lc);
    float4 pb = *(const float4*)(fcb + (size_t)lr * HW + hw0 + lc);
    *(float4*)&As[0][lr][lc] = pa;
    *(float4*)&Bs[0][lr][lc] = pb;
    __syncthreads();

    int buf = 0;
    for (int k0 = 0; k0 < DK; k0 += 8) {
        const bool has_next = (k0 + 8) < DK;
        if (has_next) {
            pa = *(const float4*)(Qm + (size_t)(k0 + 8 + lr) * DK + d0 + lc);
            pb = *(const float4*)(fcb + (size_t)(k0 + 8 + lr) * HW + hw0 + lc);
        }

#pragma unroll
        for (int k = 0; k < 8; k++) {
            float a[8], bb[8];
            *(float4*)(a)      = *(const float4*)&As[buf][k][ty * 8];
            *(float4*)(a + 4)  = *(const float4*)&As[buf][k][ty * 8 + 4];
            *(float4*)(bb)     = *(const float4*)&Bs[buf][k][tx * 8];
            *(float4*)(bb + 4) = *(const float4*)&Bs[buf][k][tx * 8 + 4];
#pragma unroll
            for (int i = 0; i < 8; i++)
#pragma unroll
                for (int j = 0; j < 8; j++) acc[i][j] += a[i] * bb[j];
        }

        if (has_next) {
            *(float4*)&As[buf ^ 1][lr][lc] = pa;
            *(float4*)&Bs[buf ^ 1][lr][lc] = pb;
            __syncthreads();
            buf ^= 1;
        }
    }

    float* qo = g_q + (size_t)b * DK * HW;
#pragma unroll
    for (int i = 0; i < 8; i++) {
        float* dst = qo + (size_t)(d0 + ty * 8 + i) * HW + hw0 + tx * 8;
        float4 v0, v1;
        v0.x = acc[i][0] * TEMP; v0.y = acc[i][1] * TEMP;
        v0.z = acc[i][2] * TEMP; v0.w = acc[i][3] * TEMP;
        v1.x = acc[i][4] * TEMP; v1.y = acc[i][5] * TEMP;
        v1.z = acc[i][6] * TEMP; v1.w = acc[i][7] * TEMP;
        *(float4*)(dst)     = v0;
        *(float4*)(dst + 4) = v1;
    }
}

// ---------------------------------------------------------------------------
// Kernel 2a: partial scores. Grid (HW/32, DQ) = 512 blocks (full chip).
// Block 512 = 32 hw lanes x 4 ms (8 m each) x 4 ds (16 d each). Each thread
// computes all 4 batches (key element loaded ONCE; 128B coalesced loads).
// result -> g_part[dq][b][m][hw].
// ---------------------------------------------------------------------------
extern __shared__ float s_red[];   // [DS][LM][NB][32] = 64KB

__global__ __launch_bounds__(512) void attn_partial_kernel(
    const float* __restrict__ key) {
    const int tid  = threadIdx.x;
    const int lane = tid & 31;           // hw
    const int ms   = (tid >> 5) & 3;     // m group (8 m)
    const int ds   = tid >> 7;           // d sub-split (16 d each)
    const int hw   = blockIdx.x * 32 + lane;
    const int dq   = blockIdx.y;
    const int dbase = dq * 64 + ds * 16;

    const float* qp[NB];
#pragma unroll
    for (int b = 0; b < NB; b++)
        qp[b] = g_q + (size_t)b * DK * HW + (size_t)dbase * HW + hw;
    const float* kp[8];
#pragma unroll
    for (int j = 0; j < 8; j++)
        kp[j] = key + (size_t)(ms * 8 + j) * DK * HW + (size_t)dbase * HW + hw;

    float acc[NB][8];
#pragma unroll
    for (int b = 0; b < NB; b++)
#pragma unroll
        for (int j = 0; j < 8; j++) acc[b][j] = 0.0f;

#pragma unroll 2
    for (int d = 0; d < 16; d++) {
        float q0 = qp[0][0], q1 = qp[1][0], q2 = qp[2][0], q3 = qp[3][0];
#pragma unroll
        for (int j = 0; j < 8; j++) {
            const float kv = kp[j][0];
            acc[0][j] += q0 * kv;
            acc[1][j] += q1 * kv;
            acc[2][j] += q2 * kv;
            acc[3][j] += q3 * kv;
        }
#pragma unroll
        for (int b = 0; b < NB; b++) qp[b] += HW;
#pragma unroll
        for (int j = 0; j < 8; j++) kp[j] += HW;
    }

    // stash partials: s_red[ds][m][b][lane]
#pragma unroll
    for (int b = 0; b < NB; b++)
#pragma unroll
        for (int j = 0; j < 8; j++)
            s_red[(((ds * LM) + ms * 8 + j) * NB + b) * 32 + lane] = acc[b][j];
    __syncthreads();

    // reduce ds and write partial: 128 threads = 32 hw x 4 b
    if (tid < 128) {
        const int b   = tid >> 5;
        const int l   = tid & 31;
        const int hwg = blockIdx.x * 32 + l;
        float* pp = g_part + (((size_t)dq * NB + b) * LM) * HW + hwg;
#pragma unroll
        for (int m = 0; m < LM; m++) {
            const float v = s_red[((0 * LM + m) * NB + b) * 32 + l]
                          + s_red[((1 * LM + m) * NB + b) * 32 + l]
                          + s_red[((2 * LM + m) * NB + b) * 32 + l]
                          + s_red[((3 * LM + m) * NB + b) * 32 + l];
            pp[(size_t)m * HW] = v;
        }
    }
}

// ---------------------------------------------------------------------------
// Kernel 2b: finish — sum DQ partials, softmax over m, write g_attn.
// Block 128 = 32 hw x 4 b, grid 128.
// ---------------------------------------------------------------------------
__global__ __launch_bounds__(128) void attn_finish_kernel() {
    const int tid = threadIdx.x;
    const int b   = tid >> 5;
    const int l   = tid & 31;
    const int hw  = blockIdx.x * 32 + l;

    float s[LM];
    float mx = -1e30f;
#pragma unroll
    for (int m = 0; m < LM; m++) {
        float v = 0.0f;
#pragma unroll
        for (int dq = 0; dq < DQ; dq++)
            v += g_part[((((size_t)dq * NB + b) * LM) + m) * HW + hw];
        s[m] = v;
        mx = fmaxf(mx, v);
    }
    float sum = 0.0f;
#pragma unroll
    for (int m = 0; m < LM; m++) { s[m] = __expf(s[m] - mx); sum += s[m]; }
    const float inv = 1.0f / sum;
    float* ap = g_attn + (size_t)b * LM * HW + hw;
#pragma unroll
    for (int m = 0; m < LM; m++) ap[(size_t)m * HW] = s[m] * inv;
}

// ---------------------------------------------------------------------------
// Kernel 3: out[b][c][hw] = fm[b][c][hw] + 0.5*sum_m attn[b][m][hw]*val[m][c][hw]
// SMEM-staged attn + float4 val loads (the R6 single change).
// Block 256 = 8 warps: warp&3 = batch, warp>>2 = c-half of a 43-wide c-chunk.
// One warp spans 128 hw (32 lanes x float4). attn tile (all 4 batches) in
// 64KB smem -> ~40 regs/thread -> 3 blocks/SM (smem-limited), 32 independent
// LDG.128 in flight per warp per c.
// Grid (32 hw-tiles, 12 c-chunks).
// ---------------------------------------------------------------------------
__global__ __launch_bounds__(256) void out_kernel(
    const float* __restrict__ fm, const float* __restrict__ val,
    float* __restrict__ out) {
    __shared__ float a_s[NB][LM][128];   // 64KB

    const int tid  = threadIdx.x;
    const int lane = tid & 31;
    const int wid  = tid >> 5;
    const int b    = wid & 3;
    const int ch   = wid >> 2;              // c-half: 0 -> 22 c's, 1 -> 21 c's
    const int hw0  = blockIdx.x * 128;
    const int c0   = blockIdx.y * 43;       // 516 = 12 * 43

    // stage attn tile: [4b][32m][128hw] — coalesced float4 fill (16 per thread)
    {
        const float* gsrc = g_attn + hw0;
        for (int i = tid; i < NB * LM * 32; i += 256) {
            const int l4  = i & 31;            // float4 index within 128 hw
            const int m   = (i >> 5) & 31;
            const int bb  = i >> 10;
            *(float4*)&a_s[bb][m][l4 * 4] =
                *(const float4*)(gsrc + ((size_t)bb * LM + m) * HW + l4 * 4);
        }
    }
    __syncthreads();

    const int cbeg = c0 + (ch ? 22 : 0);
    const int cend = c0 + (ch ? 43 : 22);

    const float* fmp = fm + (size_t)b * DV * HW + hw0 + lane * 4;
    float*       op  = out + (size_t)b * DV * HW + hw0 + lane * 4;

#pragma unroll 2
    for (int c = cbeg; c < cend; c++) {
        const float* vp = val + (size_t)c * HW + hw0 + lane * 4;
        float4 acc0 = make_float4(0.f, 0.f, 0.f, 0.f);
        float4 acc1 = make_float4(0.f, 0.f, 0.f, 0.f);
#pragma unroll
        for (int m = 0; m < LM; m += 2) {
            const float4 v0 = *(const float4*)(vp + (size_t)m * DV * HW);
            const float4 a0 = *(const float4*)&a_s[b][m][lane * 4];
            acc0.x += a0.x * v0.x;
            acc0.y += a0.y * v0.y;
            acc0.z += a0.z * v0.z;
            acc0.w += a0.w * v0.w;
            const float4 v1 = *(const float4*)(vp + (size_t)(m + 1) * DV * HW);
            const float4 a1 = *(const float4*)&a_s[b][m + 1][lane * 4];
            acc1.x += a1.x * v1.x;
            acc1.y += a1.y * v1.y;
            acc1.z += a1.z * v1.z;
            acc1.w += a1.w * v1.w;
        }
        const float4 f = *(const float4*)(fmp + (size_t)c * HW);
        float4 o;
        o.x = f.x + 0.5f * (acc0.x + acc1.x);
        o.y = f.y + 0.5f * (acc0.y + acc1.y);
        o.z = f.z + 0.5f * (acc0.z + acc1.z);
        o.w = f.w + 0.5f * (acc0.w + acc1.w);
        *(float4*)(op + (size_t)c * HW) = o;
    }
}

// ---------------------------------------------------------------------------
// Launch. Inputs (metadata order): fc, fm, key_buffer, value_buffer, Q, K, V.
// concat(new, buffer)[-32:] keeps exactly the buffers -> K and V matrices are
// dead inputs; only q = fc@Q survives.
// ---------------------------------------------------------------------------
extern "C" void kernel_launch(void* const* d_in, const int* in_sizes, int n_in,
                              void* d_out, int out_size) {
    const float* fc   = (const float*)d_in[0];
    const float* fm   = (const float*)d_in[1];
    const float* keyb = (const float*)d_in[2];
    const float* valb = (const float*)d_in[3];
    const float* Qm   = (const float*)d_in[4];
    float* out = (float*)d_out;

    const int red_bytes = DS * LM * NB * 32 * sizeof(float);   // 64KB
    cudaFuncSetAttribute(attn_partial_kernel,
                         cudaFuncAttributeMaxDynamicSharedMemorySize, red_bytes);

    qproj_kernel<<<dim3(HW / 128, DK / 128, NB), 256>>>(fc, Qm);
    attn_partial_kernel<<<dim3(HW / 32, DQ), 512, red_bytes>>>(keyb);
    attn_finish_kernel<<<dim3(HW / 32), 128>>>();
    out_kernel<<<dim3(HW / 128, 12), 256>>>(fm, valb, out);
}